// round 15
// baseline (speedup 1.0000x reference)
#include <cuda_runtime.h>
#include <cuda_fp16.h>
#include <math.h>
#include <stdint.h>

#define L   256
#define DP  128
#define DB  128
#define H   8
#define DH  32
#define HD  256      // H*DH
#define LL  (L*L)    // 65536
#define LDH (L*DH)   // 8192
#define KSPLIT 8

// smem strides (bytes)
#define ASTRIDE 144            // [row][64 halves + pad]
#define STG     (128*ASTRIDE)  // 18432 B per 128-row stage
#define BSTRIDE 272            // [row][128 halves + pad]
#define BSTG    (64*BSTRIDE)   // 17408 B per 64-row stage
#define SMEM_ROWB (3*2*STG)    // 110592 (qk)
#define SMEM_AV   (3*STG + 3*BSTG)    // 107520
#define FKBYTES  (128*BSTRIDE) // 34816
#define SMEM_PROJ (3*FKBYTES)  // 104448

// ---------------- scratch (device globals; no runtime alloc) ----------------
__device__ __half g_Pn[LL*DP];          // LN'd pair
__device__ __half g_Q [H*LL*DH];        // [h][i][n][c]
__device__ __half g_K [H*LL*DH];        // [h][j][n][c]
__device__ __half g_V [H*LL*DH];        // [h][j][k*32+d]
__device__ __half g_G [LL*HD];          // gate
__device__ float  g_Bp[H*LL];           // bias proj (fp32)
__device__ __half g_A [H*LL];           // attn probs
__device__ float  g_Apart[KSPLIT*H*LL]; // split-K logit partials (fp32)
__device__ __half g_O1[H*LL*DH];        // gated AV output
// weights TRANSPOSED [n][k], fp16
__device__ __half g_WqT[HD*DP], g_WkT[HD*DP], g_WvT[HD*DP], g_WgT[HD*DP];
__device__ __half g_WoT[DP*HD];

__device__ __forceinline__ float fixnum(float x){
    if (isnan(x)) return 0.f;
    if (isinf(x)) return x > 0.f ? 3.4028234663852886e38f : -3.4028234663852886e38f;
    return x;
}

__device__ __forceinline__ void mma_f16(float c[4],
        uint32_t a0, uint32_t a1, uint32_t a2, uint32_t a3,
        uint32_t b0, uint32_t b1){
    asm volatile(
        "mma.sync.aligned.m16n8k16.row.col.f32.f16.f16.f32 "
        "{%0,%1,%2,%3},{%4,%5,%6,%7},{%8,%9},{%0,%1,%2,%3};"
        : "+f"(c[0]), "+f"(c[1]), "+f"(c[2]), "+f"(c[3])
        : "r"(a0), "r"(a1), "r"(a2), "r"(a3), "r"(b0), "r"(b1));
}
__device__ __forceinline__ void cpa16(uint32_t s_dst, const void* g_src){
    asm volatile("cp.async.cg.shared.global [%0], [%1], 16;" :: "r"(s_dst), "l"(g_src));
}
#define CP_COMMIT asm volatile("cp.async.commit_group;")
#define CP_WAIT1  asm volatile("cp.async.wait_group 1;")
#define CP_WAIT0  asm volatile("cp.async.wait_group 0;")

__device__ __forceinline__ void ldsm4(uint32_t addr,
        uint32_t& r0, uint32_t& r1, uint32_t& r2, uint32_t& r3){
    asm volatile("ldmatrix.sync.aligned.m8n8.x4.shared.b16 {%0,%1,%2,%3}, [%4];"
        : "=r"(r0), "=r"(r1), "=r"(r2), "=r"(r3) : "r"(addr));
}
__device__ __forceinline__ void ldsm2t(uint32_t addr, uint32_t& r0, uint32_t& r1){
    asm volatile("ldmatrix.sync.aligned.m8n8.x2.trans.shared.b16 {%0,%1}, [%2];"
        : "=r"(r0), "=r"(r1) : "r"(addr));
}

// -------- kernel 0: fp16 + transpose weights ---------------------------------
__global__ void cvt_weights(const float* __restrict__ Wq, const float* __restrict__ Wk,
                            const float* __restrict__ Wv, const float* __restrict__ Wg,
                            const float* __restrict__ Wo){
    int j = blockIdx.x*256 + threadIdx.x;   // 32768
    int mm = j >> 7, d = j & 127;
    int src = d*HD + mm;
    g_WqT[j] = __float2half_rn(Wq[src]); g_WkT[j] = __float2half_rn(Wk[src]);
    g_WvT[j] = __float2half_rn(Wv[src]); g_WgT[j] = __float2half_rn(Wg[src]);
    int col = j >> 8, m = j & 255;
    g_WoT[j] = __float2half_rn(Wo[m*DP + col]);
}

// -------- kernel 1: nan_to_num + transpose + layernorm of pair --------------
__global__ void ln_pair_kernel(const float* __restrict__ pair,
                               const float* __restrict__ g,
                               const float* __restrict__ b,
                               int blk_base){
    int m = (blockIdx.x + blk_base)*8 + (threadIdx.x >> 5);   // row = a*L + b2
    int lane = threadIdx.x & 31;
    int a = m >> 8, b2 = m & 255;
    float4 x = *(const float4*)&pair[((size_t)b2*L + a)*DP + lane*4];
    x.x = fixnum(x.x); x.y = fixnum(x.y); x.z = fixnum(x.z); x.w = fixnum(x.w);
    float s = x.x + x.y + x.z + x.w;
    #pragma unroll
    for (int o = 16; o > 0; o >>= 1) s += __shfl_xor_sync(0xffffffffu, s, o);
    float mean = s * (1.f/DP);
    float c0 = x.x-mean, c1 = x.y-mean, c2 = x.z-mean, c3 = x.w-mean;
    float q = c0*c0 + c1*c1 + c2*c2 + c3*c3;
    #pragma unroll
    for (int o = 16; o > 0; o >>= 1) q += __shfl_xor_sync(0xffffffffu, q, o);
    float rs = rsqrtf(q * (1.f/DP) + 1e-5f);
    float4 gv = *(const float4*)&g[lane*4];
    float4 bv = *(const float4*)&b[lane*4];
    __half2 h01 = __floats2half2_rn(c0*rs*gv.x + bv.x, c1*rs*gv.y + bv.y);
    __half2 h23 = __floats2half2_rn(c2*rs*gv.z + bv.z, c3*rs*gv.w + bv.w);
    uint2 pk;
    pk.x = *(uint32_t*)&h01; pk.y = *(uint32_t*)&h23;
    *(uint2*)&g_Pn[(size_t)m*DP + lane*4] = pk;
}

// -------- kernel 2: bias LN + projection to per-head bias -------------------
__global__ void bias_proj_kernel(const float* __restrict__ bias,
                                 const float* __restrict__ g,
                                 const float* __restrict__ bb,
                                 const float* __restrict__ Wb){
    int bid = blockIdx.x;           // i*L + j
    int i = bid >> 8, j = bid & 255;
    int e = threadIdx.x;            // 128
    float x = fixnum(bias[(j*L + i)*DB + e]);
    __shared__ float ws[4];
    __shared__ float xn[128];
    __shared__ float red[128];
    float s = x;
    #pragma unroll
    for (int o = 16; o > 0; o >>= 1) s += __shfl_xor_sync(0xffffffffu, s, o);
    if ((e & 31) == 0) ws[e >> 5] = s;
    __syncthreads();
    float m = (ws[0]+ws[1]+ws[2]+ws[3]) * (1.f/DB);
    float c = x - m;
    float q = c*c;
    #pragma unroll
    for (int o = 16; o > 0; o >>= 1) q += __shfl_xor_sync(0xffffffffu, q, o);
    __syncthreads();
    if ((e & 31) == 0) ws[e >> 5] = q;
    __syncthreads();
    float v = (ws[0]+ws[1]+ws[2]+ws[3]) * (1.f/DB);
    xn[e] = c * rsqrtf(v + 1e-5f) * g[e] + bb[e];
    __syncthreads();
    int h = e & 7;
    int es = e >> 3;
    float acc = 0.f;
    #pragma unroll
    for (int ss = 0; ss < 8; ss++){
        int ee = es + ss*16;
        acc += xn[ee] * Wb[ee*H + h];
    }
    red[e] = acc; __syncthreads();
    if (e < 8){
        float t = 0.f;
        #pragma unroll
        for (int ss = 0; ss < 16; ss++) t += red[e + ss*8];
        g_Bp[(e*L + i)*L + j] = t;
    }
}

// ================= fp16 mma.sync GEMM cores ==================================
#define LDSM_OFFS                                                              \
    const uint32_t aoff = (((lane & 7) + ((lane >> 3) & 1)*8)*ASTRIDE          \
                           + (lane >> 4)*16);                                  \
    const uint32_t boff4 = ((lane & 7)*ASTRIDE + ((lane >> 3) & 1)*16          \
                           + (lane >> 4)*8*ASTRIDE);
#define LDSM_OFFS_FK                                                           \
    const uint32_t aoff2 = (((lane & 7) + ((lane >> 3) & 1)*8)*BSTRIDE         \
                            + (lane >> 4)*16);                                 \
    const uint32_t boff4_2 = ((lane & 7)*BSTRIDE + ((lane >> 3) & 1)*16        \
                             + (lane >> 4)*8*BSTRIDE);

#define COMPUTE_ROWB_F16(aBase, bBase)                                         \
    _Pragma("unroll")                                                          \
    for (int kk8 = 0; kk8 < 4; kk8++){                                         \
        uint32_t ksb = kk8*32;                                                 \
        uint32_t a[4][4], b[4][2];                                             \
        _Pragma("unroll")                                                      \
        for (int mt = 0; mt < 4; mt++)                                         \
            ldsm4((aBase) + (wm + mt*16)*ASTRIDE + ksb + aoff,                 \
                  a[mt][0], a[mt][1], a[mt][2], a[mt][3]);                     \
        _Pragma("unroll")                                                      \
        for (int ntp = 0; ntp < 2; ntp++)                                      \
            ldsm4((bBase) + (wn + ntp*16)*ASTRIDE + ksb + boff4,               \
                  b[2*ntp][0], b[2*ntp][1], b[2*ntp+1][0], b[2*ntp+1][1]);     \
        _Pragma("unroll")                                                      \
        for (int mt = 0; mt < 4; mt++)                                         \
            _Pragma("unroll")                                                  \
            for (int nt = 0; nt < 4; nt++)                                     \
                mma_f16(c[mt][nt], a[mt][0],a[mt][1],a[mt][2],a[mt][3],        \
                        b[nt][0], b[nt][1]);                                   \
    }

#define COMPUTE_FK_F16(aBase, bBase)                                           \
    _Pragma("unroll")                                                          \
    for (int kk8 = 0; kk8 < 8; kk8++){                                         \
        uint32_t ksb = kk8*32;                                                 \
        uint32_t a[4][4], b[4][2];                                             \
        _Pragma("unroll")                                                      \
        for (int mt = 0; mt < 4; mt++)                                         \
            ldsm4((aBase) + (wm + mt*16)*BSTRIDE + ksb + aoff2,                \
                  a[mt][0], a[mt][1], a[mt][2], a[mt][3]);                     \
        _Pragma("unroll")                                                      \
        for (int ntp = 0; ntp < 2; ntp++)                                      \
            ldsm4((bBase) + (wn + ntp*16)*BSTRIDE + ksb + boff4_2,             \
                  b[2*ntp][0], b[2*ntp][1], b[2*ntp+1][0], b[2*ntp+1][1]);     \
        _Pragma("unroll")                                                      \
        for (int mt = 0; mt < 4; mt++)                                         \
            _Pragma("unroll")                                                  \
            for (int nt = 0; nt < 4; nt++)                                     \
                mma_f16(c[mt][nt], a[mt][0],a[mt][1],a[mt][2],a[mt][3],        \
                        b[nt][0], b[nt][1]);                                   \
    }

#define COMPUTE_KNB_F16(aBase, bBase)                                          \
    _Pragma("unroll")                                                          \
    for (int kk8 = 0; kk8 < 4; kk8++){                                         \
        uint32_t ksb = kk8*32;                                                 \
        uint32_t a[4][4], b[4][2];                                             \
        _Pragma("unroll")                                                      \
        for (int mt = 0; mt < 4; mt++)                                         \
            ldsm4((aBase) + (wm + mt*16)*ASTRIDE + ksb + aoff,                 \
                  a[mt][0], a[mt][1], a[mt][2], a[mt][3]);                     \
        _Pragma("unroll")                                                      \
        for (int nt = 0; nt < 4; nt++)                                         \
            ldsm2t((bBase) + (kk8*16 + (lane & 15))*BSTRIDE + (wn + nt*8)*2,   \
                   b[nt][0], b[nt][1]);                                        \
        _Pragma("unroll")                                                      \
        for (int mt = 0; mt < 4; mt++)                                         \
            _Pragma("unroll")                                                  \
            for (int nt = 0; nt < 4; nt++)                                     \
                mma_f16(c[mt][nt], a[mt][0],a[mt][1],a[mt][2],a[mt][3],        \
                        b[nt][0], b[nt][1]);                                   \
    }

// -------- kernel 3: projection GEMM, A-resident, 4 n-tiles per CTA -----------
__global__ __launch_bounds__(256) void proj_mma(const float* __restrict__ bg,
                                                int half_sel, int r_base){
    extern __shared__ char smem[];
    uint32_t sb = (uint32_t)__cvta_generic_to_shared(smem);
    uint32_t sA = sb;
    uint32_t sBb[2] = { sb + FKBYTES, sb + 2*FKBYTES };

    int tid = threadIdx.x;
    int warp = tid >> 5, lane = tid & 31;
    int gid = lane >> 2, tig = lane & 3;
    LDSM_OFFS_FK
    int r0 = (blockIdx.x + r_base) * 128;
    int wm = (warp >> 2) * 64, wn = (warp & 3) * 32;

    #pragma unroll
    for (int it = 0; it < 8; it++){
        int idx = tid + it*256;
        int row = idx >> 4, kq = idx & 15;
        cpa16(sA + row*BSTRIDE + kq*16, &g_Pn[(size_t)(r0+row)*DP + kq*8]);
    }
    CP_COMMIT;

    auto loadB = [&](int t){
        int n0g = half_sel*512 + t*128;
        int which = n0g >> 8;
        const __half* WT = (which==0)?g_WqT:(which==1)?g_WkT:(which==2)?g_WvT:g_WgT;
        int nn0 = n0g & 255;
        uint32_t dst = sBb[t & 1];
        #pragma unroll
        for (int it = 0; it < 8; it++){
            int idx = tid + it*256;
            int row = idx >> 4, kq = idx & 15;
            cpa16(dst + row*BSTRIDE + kq*16, &WT[(size_t)(nn0+row)*DP + kq*8]);
        }
    };
    loadB(0); CP_COMMIT;
    loadB(1); CP_COMMIT;

    const float SQ = 0.17677669529663687f;  // 1/sqrt(DH)
    const float SK = 0.0625f;               // 1/sqrt(L)

    for (int t = 0; t < 4; t++){
        if (t < 3) { CP_WAIT1; } else { CP_WAIT0; }
        __syncthreads();
        float c[4][4][4] = {};
        uint32_t bB = sBb[t & 1];
        COMPUTE_FK_F16(sA, bB);

        int n0g = half_sel*512 + t*128;
        int which = n0g >> 8;
        int nn0 = n0g & 255;
        #pragma unroll
        for (int mt = 0; mt < 4; mt++){
            #pragma unroll
            for (int nt = 0; nt < 4; nt++){
                #pragma unroll
                for (int half = 0; half < 2; half++){
                    int row = r0 + wm + mt*16 + gid + half*8;
                    int a_ = row >> 8, b2 = row & 255;
                    int mm = nn0 + wn + nt*8 + 2*tig;
                    float y0 = c[mt][nt][half*2+0];
                    float y1 = c[mt][nt][half*2+1];
                    if (which == 3){
                        y0 = 1.f/(1.f + expf(-(y0 + bg[mm])));
                        y1 = 1.f/(1.f + expf(-(y1 + bg[mm+1])));
                        __half2 hv = __floats2half2_rn(y0, y1);
                        *(__half2*)&g_G[(size_t)row*HD + mm] = hv;
                    } else {
                        int hh = mm >> 5, cc = mm & 31;
                        size_t dst = (((size_t)hh*L + b2)*L + a_)*DH + cc;
                        float sc = (which==0) ? SQ : (which==1) ? SK : 1.f;
                        __half2 hv = __floats2half2_rn(y0*sc, y1*sc);
                        if      (which==0) *(__half2*)&g_Q[dst] = hv;
                        else if (which==1) *(__half2*)&g_K[dst] = hv;
                        else               *(__half2*)&g_V[dst] = hv;
                    }
                }
            }
        }
        __syncthreads();            // all warps done reading buf (t&1)
        if (t + 2 < 4) loadB(t + 2);
        CP_COMMIT;
    }
}

// -------- kernel 4: QK^T logits, split-K -------------------------------------
__global__ __launch_bounds__(256) void qk_mma(int ks_base){
    extern __shared__ char smem[];
    uint32_t sb = (uint32_t)__cvta_generic_to_shared(smem);
    uint32_t sA = sb, sB = sb + 3*STG;

    int tid = threadIdx.x;
    int warp = tid >> 5, lane = tid & 31;
    int gid = lane >> 2, tig = lane & 3;
    LDSM_OFFS
    int ks_id = blockIdx.x + ks_base;
    int tile  = blockIdx.y;
    int i0 = (tile >> 1) * 128, j0 = (tile & 1) * 128;
    int h = blockIdx.z;
    const __half* Qh = g_Q + (size_t)h * (LL*DH);
    const __half* Kh = g_K + (size_t)h * (LL*DH);
    int wm = (warp >> 2) * 64, wn = (warp & 3) * 32;
    float c[4][4][4] = {};
    int kbeg = ks_id * 1024;             // halves

    auto load_stage = [&](int t, int slot){
        int k0 = kbeg + t * 64;
        #pragma unroll
        for (int it = 0; it < 4; it++){
            int idx = tid + it*256;
            int row = idx >> 3, kq = idx & 7;
            cpa16(sA + slot*STG + row*ASTRIDE + kq*16,
                  &Qh[(size_t)(i0+row)*LDH + k0 + kq*8]);
            cpa16(sB + slot*STG + row*ASTRIDE + kq*16,
                  &Kh[(size_t)(j0+row)*LDH + k0 + kq*8]);
        }
    };
    const int NS = 16;
    load_stage(0,0); CP_COMMIT;
    load_stage(1,1); CP_COMMIT;
    for (int s = 0; s < NS; s++){
        CP_WAIT1; __syncthreads();
        if (s + 2 < NS) load_stage(s+2, (s+2)%3);
        CP_COMMIT;
        uint32_t aB = sA + (s%3)*STG, bB = sB + (s%3)*STG;
        COMPUTE_ROWB_F16(aB, bB);
    }

    float* dst = g_Apart + ((size_t)ks_id*H + h) * LL;
    #pragma unroll
    for (int mt = 0; mt < 4; mt++)
        #pragma unroll
        for (int nt = 0; nt < 4; nt++)
            #pragma unroll
            for (int half = 0; half < 2; half++){
                int i = i0 + wm + mt*16 + gid + half*8;
                int j = j0 + wn + nt*8 + 2*tig;
                *(float2*)&dst[(size_t)i*L + j] =
                    make_float2(c[mt][nt][half*2], c[mt][nt][half*2+1]);
            }
}

// -------- kernel 5: reduce split-K + bias + mask + softmax (shfl) ------------
__global__ __launch_bounds__(256) void softmax_fused(const int* __restrict__ mask,
                                                     int i_base){
    int h = blockIdx.x >> 7;
    int i = i_base + (blockIdx.x & 127);
    int row = h*L + i;
    int j = threadIdx.x;       // 256
    int lane = j & 31, warp = j >> 5;
    float v = 0.f;
    #pragma unroll
    for (int s = 0; s < KSPLIT; s++)
        v += g_Apart[(((size_t)s*H + h)*L + i)*L + j];
    v += g_Bp[(size_t)row*L + j];
    if (mask[i] == 0 || mask[j] == 0) v = -1e9f;

    __shared__ float wred[8];
    float mx = v;
    #pragma unroll
    for (int o = 16; o > 0; o >>= 1) mx = fmaxf(mx, __shfl_xor_sync(0xffffffffu, mx, o));
    if (lane == 0) wred[warp] = mx;
    __syncthreads();
    float m0 = wred[lane & 7];
    #pragma unroll
    for (int o = 4; o > 0; o >>= 1) m0 = fmaxf(m0, __shfl_xor_sync(0xffffffffu, m0, o));
    mx = m0;

    float e = expf(v - mx);
    float sm = e;
    #pragma unroll
    for (int o = 16; o > 0; o >>= 1) sm += __shfl_xor_sync(0xffffffffu, sm, o);
    __syncthreads();
    if (lane == 0) wred[warp] = sm;
    __syncthreads();
    float s0 = wred[lane & 7];
    #pragma unroll
    for (int o = 4; o > 0; o >>= 1) s0 += __shfl_xor_sync(0xffffffffu, s0, o);
    g_A[(size_t)row*L + j] = __float2half_rn(e / s0);
}

// -------- kernel 6: AV GEMM + gate (KNB, trans-LDSM on V) --------------------
__global__ __launch_bounds__(256) void av_mma(int i0_base){
    extern __shared__ char smem[];
    uint32_t sb = (uint32_t)__cvta_generic_to_shared(smem);
    uint32_t sA = sb, sB = sb + 3*STG;

    int tid = threadIdx.x;
    int warp = tid >> 5, lane = tid & 31;
    int gid = lane >> 2, tig = lane & 3;
    LDSM_OFFS
    (void)boff4;
    int n0 = blockIdx.x * 128;
    int i0 = i0_base;
    int h  = blockIdx.z;
    const __half* Ah = g_A + (size_t)h * LL;
    const __half* Vh = g_V + (size_t)h * (LL*DH);
    int wm = (warp >> 2) * 64, wn = (warp & 3) * 32;
    float c[4][4][4] = {};

    auto load_stage = [&](int t, int slot){
        int k0 = t * 64;                 // j offset
        #pragma unroll
        for (int it = 0; it < 4; it++){
            int idx = tid + it*256;
            int row = idx >> 3, kq = idx & 7;
            cpa16(sA + slot*STG + row*ASTRIDE + kq*16,
                  &Ah[(size_t)(i0+row)*L + k0 + kq*8]);
            int jl = idx >> 4, nq = idx & 15;
            cpa16(sB + slot*BSTG + jl*BSTRIDE + nq*16,
                  &Vh[(size_t)(k0+jl)*LDH + n0 + nq*8]);
        }
    };
    const int NS = 4;
    load_stage(0,0); CP_COMMIT;
    load_stage(1,1); CP_COMMIT;
    for (int s = 0; s < NS; s++){
        CP_WAIT1; __syncthreads();
        if (s + 2 < NS) load_stage(s+2, (s+2)%3);
        CP_COMMIT;
        uint32_t aB = sA + (s%3)*STG, bB = sB + (s%3)*BSTG;
        COMPUTE_KNB_F16(aB, bB);
    }

    __half* Oh = g_O1 + (size_t)h * (LL*DH);
    #pragma unroll
    for (int mt = 0; mt < 4; mt++)
        #pragma unroll
        for (int nt = 0; nt < 4; nt++)
            #pragma unroll
            for (int half = 0; half < 2; half++){
                int i = i0 + wm + mt*16 + gid + half*8;
                int n = n0 + wn + nt*8 + 2*tig;
                __half2 gg = *(const __half2*)&g_G[((size_t)i*L + (n>>5))*HD + h*DH + (n&31)];
                float2 gf = __half22float2(gg);
                __half2 hv = __floats2half2_rn(c[mt][nt][half*2]   * gf.x,
                                               c[mt][nt][half*2+1] * gf.y);
                *(__half2*)&Oh[(size_t)i*LDH + n] = hv;
            }
}

// -------- kernel 7: (gated out) @ Wo + bo (ROWB via WoT) ----------------------
__global__ __launch_bounds__(256) void final_mma(
        const int* __restrict__ mask, const float* __restrict__ bo,
        float* __restrict__ out, int blk_base){
    extern __shared__ char smem[];
    uint32_t sb = (uint32_t)__cvta_generic_to_shared(smem);
    uint32_t sA = sb, sB = sb + 3*STG;

    int tid = threadIdx.x;
    int warp = tid >> 5, lane = tid & 31;
    int gid = lane >> 2, tig = lane & 3;
    LDSM_OFFS
    int r0 = (blockIdx.x + blk_base) * 128;   // rows r = i*256 + k
    int i  = r0 >> 8;
    int k0r = r0 & 255;
    int wm = (warp >> 2) * 64, wn = (warp & 3) * 32;
    float c[4][4][4] = {};

    auto load_stage = [&](int t, int slot){
        #pragma unroll
        for (int it = 0; it < 4; it++){
            int idx = tid + it*256;
            int row = idx >> 3, kq = idx & 7;
            int hh = 2*t + (kq >> 2), d = (kq & 3)*8;
            cpa16(sA + slot*STG + row*ASTRIDE + kq*16,
                  &g_O1[(size_t)hh*(LL*DH) + (size_t)i*LDH
                        + (size_t)(k0r+row)*DH + d]);
            cpa16(sB + slot*STG + row*ASTRIDE + kq*16,
                  &g_WoT[(size_t)row*HD + t*64 + kq*8]);
        }
    };
    const int NS = 4;
    load_stage(0,0); CP_COMMIT;
    load_stage(1,1); CP_COMMIT;
    for (int s = 0; s < NS; s++){
        CP_WAIT1; __syncthreads();
        if (s + 2 < NS) load_stage(s+2, (s+2)%3);
        CP_COMMIT;
        uint32_t aB = sA + (s%3)*STG, bB = sB + (s%3)*STG;
        COMPUTE_ROWB_F16(aB, bB);
    }

    bool mi = (mask[i] == 0);
    #pragma unroll
    for (int mt = 0; mt < 4; mt++)
        #pragma unroll
        for (int nt = 0; nt < 4; nt++)
            #pragma unroll
            for (int half = 0; half < 2; half++){
                int rowl = wm + mt*16 + gid + half*8;
                int k = k0r + rowl;
                int col = wn + nt*8 + 2*tig;
                float y0 = c[mt][nt][half*2+0] + bo[col];
                float y1 = c[mt][nt][half*2+1] + bo[col+1];
                if (mi || mask[k] == 0){ y0 = 0.f; y1 = 0.f; }
                *(float2*)&out[((size_t)k*L + i)*DP + col] = make_float2(y0, y1);
            }
}

// ---------------------------------------------------------------------------
extern "C" void kernel_launch(void* const* d_in, const int* in_sizes, int n_in,
                              void* d_out, int out_size){
    const float* pair   = (const float*)d_in[0];
    const float* bias   = (const float*)d_in[1];
    const int*   mask   = (const int*)  d_in[2];
    const float* g_pair = (const float*)d_in[3];
    const float* b_pair = (const float*)d_in[4];
    const float* g_bias = (const float*)d_in[5];
    const float* b_bias = (const float*)d_in[6];
    const float* Wq     = (const float*)d_in[7];
    const float* Wk     = (const float*)d_in[8];
    const float* Wv     = (const float*)d_in[9];
    const float* Wb     = (const float*)d_in[10];
    const float* Wg     = (const float*)d_in[11];
    const float* bg     = (const float*)d_in[12];
    const float* Wo     = (const float*)d_in[13];
    const float* bo     = (const float*)d_in[14];
    float* out = (float*)d_out;

    static int inited = 0;
    static cudaStream_t s2, s3;
    static cudaEvent_t ev0, ev1a, ev1, ev2, ev3, evB, evQK, ev5;
    if (!inited){
        cudaFuncSetAttribute(proj_mma,  cudaFuncAttributeMaxDynamicSharedMemorySize, SMEM_PROJ);
        cudaFuncSetAttribute(qk_mma,    cudaFuncAttributeMaxDynamicSharedMemorySize, SMEM_ROWB);
        cudaFuncSetAttribute(av_mma,    cudaFuncAttributeMaxDynamicSharedMemorySize, SMEM_AV);
        cudaFuncSetAttribute(final_mma, cudaFuncAttributeMaxDynamicSharedMemorySize, SMEM_ROWB);
        cudaStreamCreateWithFlags(&s2, cudaStreamNonBlocking);
        cudaStreamCreateWithFlags(&s3, cudaStreamNonBlocking);
        cudaEventCreateWithFlags(&ev0,  cudaEventDisableTiming);
        cudaEventCreateWithFlags(&ev1a, cudaEventDisableTiming);
        cudaEventCreateWithFlags(&ev1,  cudaEventDisableTiming);
        cudaEventCreateWithFlags(&ev2,  cudaEventDisableTiming);
        cudaEventCreateWithFlags(&ev3,  cudaEventDisableTiming);
        cudaEventCreateWithFlags(&evB,  cudaEventDisableTiming);
        cudaEventCreateWithFlags(&evQK, cudaEventDisableTiming);
        cudaEventCreateWithFlags(&ev5,  cudaEventDisableTiming);
        inited = 1;
    }

    // fork side streams
    cudaEventRecord(ev0, 0);
    cudaStreamWaitEvent(s2, ev0, 0);
    cudaStreamWaitEvent(s3, ev0, 0);

    bias_proj_kernel<<<LL, 128, 0, s2>>>(bias, g_bias, b_bias, Wb);  // inputs only
    cvt_weights     <<<128, 256, 0, s3>>>(Wq, Wk, Wv, Wg, Wo);       // inputs only
    cudaEventRecord(ev3, s3);

    // ln in two halves: a<128 first so projQK_A can start early
    ln_pair_kernel  <<<4096, 256>>>(pair, g_pair, b_pair, 0);
    cudaEventRecord(ev1a, 0);
    ln_pair_kernel  <<<4096, 256>>>(pair, g_pair, b_pair, 4096);
    cudaEventRecord(ev1, 0);

    // projQK_B (rows a>=128) on s3 — co-runs with projQK_A / qk_A
    cudaStreamWaitEvent(s3, ev1, 0);
    proj_mma        <<<256, 256, SMEM_PROJ, s3>>>(bg, 0, 256);
    cudaEventRecord(evB, s3);

    // projVG (all rows) on s2 — needs full ln + weights
    cudaStreamWaitEvent(s2, ev1, 0);
    cudaStreamWaitEvent(s2, ev3, 0);
    proj_mma        <<<512, 256, SMEM_PROJ, s2>>>(bg, 1, 0);   // V, G
    cudaEventRecord(ev2, s2);

    // main: projQK_A (rows a<128) needs ln_A + weights
    cudaStreamWaitEvent(0, ev3, 0);
    // note: main already ordered after ln_A in-stream
    proj_mma        <<<256, 256, SMEM_PROJ>>>(bg, 0, 0);
    qk_mma          <<<dim3(4, 4, H), 256, SMEM_ROWB>>>(0);    // ks 0..3 (n<128)
    cudaStreamWaitEvent(0, evB, 0);
    qk_mma          <<<dim3(4, 4, H), 256, SMEM_ROWB>>>(4);    // ks 4..7
    cudaEventRecord(evQK, 0);

    // tail pipeline: halves by i
    cudaStreamWaitEvent(0, ev2, 0);                 // Bp + V + G ready
    softmax_fused   <<<1024, 256>>>(mask, 0);       // i < 128
    av_mma          <<<dim3(64, 1, H), 256, SMEM_AV>>>(0);
    // s2: second half (Bp, V, G in-stream; logits via evQK)
    cudaStreamWaitEvent(s2, evQK, 0);
    softmax_fused   <<<1024, 256, 0, s2>>>(mask, 128);   // i >= 128
    av_mma          <<<dim3(64, 1, H), 256, SMEM_AV, s2>>>(128);
    cudaEventRecord(ev5, s2);

    final_mma       <<<256, 256, SMEM_ROWB>>>(mask, bo, out, 0);    // i < 128
    cudaStreamWaitEvent(0, ev5, 0);
    final_mma       <<<256, 256, SMEM_ROWB>>>(mask, bo, out, 256);  // i >= 128
}

// round 16
// speedup vs baseline: 1.0153x; 1.0153x over previous
#include <cuda_runtime.h>
#include <cuda_fp16.h>
#include <math.h>
#include <stdint.h>

#define L   256
#define DP  128
#define DB  128
#define H   8
#define DH  32
#define HD  256      // H*DH
#define LL  (L*L)    // 65536
#define LDH (L*DH)   // 8192
#define KSPLIT 8

// smem strides (bytes)
#define ASTRIDE 144            // [row][64 halves + pad]
#define STG     (128*ASTRIDE)  // 18432 B per 128-row stage
#define BSTRIDE 272            // [row][128 halves + pad]
#define BSTG    (64*BSTRIDE)   // 17408 B per 64-row stage
#define SMEM_ROWB (3*2*STG)    // 110592 (qk)
#define SMEM_AV   (3*STG + 3*BSTG)    // 107520
#define FKBYTES  (128*BSTRIDE) // 34816
#define SMEM_PROJ (3*FKBYTES)  // 104448

// ---------------- scratch (device globals; no runtime alloc) ----------------
__device__ __half g_Pn[LL*DP];          // LN'd pair
__device__ __half g_Q [H*LL*DH];        // [h][i][n][c]
__device__ __half g_K [H*LL*DH];        // [h][j][n][c]
__device__ __half g_V [H*LL*DH];        // [h][j][k*32+d]
__device__ __half g_G [LL*HD];          // gate
__device__ float  g_Bp[H*LL];           // bias proj (fp32)
__device__ __half g_A [H*LL];           // attn probs
__device__ float  g_Apart[KSPLIT*H*LL]; // split-K logit partials (fp32)
__device__ __half g_O1[H*LL*DH];        // gated AV output
// weights TRANSPOSED [n][k], fp16
__device__ __half g_WqT[HD*DP], g_WkT[HD*DP], g_WvT[HD*DP], g_WgT[HD*DP];
__device__ __half g_WoT[DP*HD];

__device__ __forceinline__ float fixnum(float x){
    if (isnan(x)) return 0.f;
    if (isinf(x)) return x > 0.f ? 3.4028234663852886e38f : -3.4028234663852886e38f;
    return x;
}

__device__ __forceinline__ void mma_f16(float c[4],
        uint32_t a0, uint32_t a1, uint32_t a2, uint32_t a3,
        uint32_t b0, uint32_t b1){
    asm volatile(
        "mma.sync.aligned.m16n8k16.row.col.f32.f16.f16.f32 "
        "{%0,%1,%2,%3},{%4,%5,%6,%7},{%8,%9},{%0,%1,%2,%3};"
        : "+f"(c[0]), "+f"(c[1]), "+f"(c[2]), "+f"(c[3])
        : "r"(a0), "r"(a1), "r"(a2), "r"(a3), "r"(b0), "r"(b1));
}
__device__ __forceinline__ void cpa16(uint32_t s_dst, const void* g_src){
    asm volatile("cp.async.cg.shared.global [%0], [%1], 16;" :: "r"(s_dst), "l"(g_src));
}
#define CP_COMMIT asm volatile("cp.async.commit_group;")
#define CP_WAIT1  asm volatile("cp.async.wait_group 1;")
#define CP_WAIT0  asm volatile("cp.async.wait_group 0;")

__device__ __forceinline__ void ldsm4(uint32_t addr,
        uint32_t& r0, uint32_t& r1, uint32_t& r2, uint32_t& r3){
    asm volatile("ldmatrix.sync.aligned.m8n8.x4.shared.b16 {%0,%1,%2,%3}, [%4];"
        : "=r"(r0), "=r"(r1), "=r"(r2), "=r"(r3) : "r"(addr));
}
__device__ __forceinline__ void ldsm2t(uint32_t addr, uint32_t& r0, uint32_t& r1){
    asm volatile("ldmatrix.sync.aligned.m8n8.x2.trans.shared.b16 {%0,%1}, [%2];"
        : "=r"(r0), "=r"(r1) : "r"(addr));
}

// -------- kernel 0: fp16 + transpose weights ---------------------------------
__global__ void cvt_weights(const float* __restrict__ Wq, const float* __restrict__ Wk,
                            const float* __restrict__ Wv, const float* __restrict__ Wg,
                            const float* __restrict__ Wo){
    int j = blockIdx.x*256 + threadIdx.x;   // 32768
    int mm = j >> 7, d = j & 127;
    int src = d*HD + mm;
    g_WqT[j] = __float2half_rn(Wq[src]); g_WkT[j] = __float2half_rn(Wk[src]);
    g_WvT[j] = __float2half_rn(Wv[src]); g_WgT[j] = __float2half_rn(Wg[src]);
    int col = j >> 8, m = j & 255;
    g_WoT[j] = __float2half_rn(Wo[m*DP + col]);
}

// -------- kernel 1: nan_to_num + transpose + layernorm of pair --------------
__global__ void ln_pair_kernel(const float* __restrict__ pair,
                               const float* __restrict__ g,
                               const float* __restrict__ b){
    int m = blockIdx.x*8 + (threadIdx.x >> 5);   // row = a*L + b2
    int lane = threadIdx.x & 31;
    int a = m >> 8, b2 = m & 255;
    float4 x = *(const float4*)&pair[((size_t)b2*L + a)*DP + lane*4];
    x.x = fixnum(x.x); x.y = fixnum(x.y); x.z = fixnum(x.z); x.w = fixnum(x.w);
    float s = x.x + x.y + x.z + x.w;
    #pragma unroll
    for (int o = 16; o > 0; o >>= 1) s += __shfl_xor_sync(0xffffffffu, s, o);
    float mean = s * (1.f/DP);
    float c0 = x.x-mean, c1 = x.y-mean, c2 = x.z-mean, c3 = x.w-mean;
    float q = c0*c0 + c1*c1 + c2*c2 + c3*c3;
    #pragma unroll
    for (int o = 16; o > 0; o >>= 1) q += __shfl_xor_sync(0xffffffffu, q, o);
    float rs = rsqrtf(q * (1.f/DP) + 1e-5f);
    float4 gv = *(const float4*)&g[lane*4];
    float4 bv = *(const float4*)&b[lane*4];
    __half2 h01 = __floats2half2_rn(c0*rs*gv.x + bv.x, c1*rs*gv.y + bv.y);
    __half2 h23 = __floats2half2_rn(c2*rs*gv.z + bv.z, c3*rs*gv.w + bv.w);
    uint2 pk;
    pk.x = *(uint32_t*)&h01; pk.y = *(uint32_t*)&h23;
    *(uint2*)&g_Pn[(size_t)m*DP + lane*4] = pk;
}

// -------- kernel 2: bias LN + projection to per-head bias -------------------
__global__ void bias_proj_kernel(const float* __restrict__ bias,
                                 const float* __restrict__ g,
                                 const float* __restrict__ bb,
                                 const float* __restrict__ Wb){
    int bid = blockIdx.x;           // i*L + j
    int i = bid >> 8, j = bid & 255;
    int e = threadIdx.x;            // 128
    float x = fixnum(bias[(j*L + i)*DB + e]);
    __shared__ float ws[4];
    __shared__ float xn[128];
    __shared__ float red[128];
    float s = x;
    #pragma unroll
    for (int o = 16; o > 0; o >>= 1) s += __shfl_xor_sync(0xffffffffu, s, o);
    if ((e & 31) == 0) ws[e >> 5] = s;
    __syncthreads();
    float m = (ws[0]+ws[1]+ws[2]+ws[3]) * (1.f/DB);
    float c = x - m;
    float q = c*c;
    #pragma unroll
    for (int o = 16; o > 0; o >>= 1) q += __shfl_xor_sync(0xffffffffu, q, o);
    __syncthreads();
    if ((e & 31) == 0) ws[e >> 5] = q;
    __syncthreads();
    float v = (ws[0]+ws[1]+ws[2]+ws[3]) * (1.f/DB);
    xn[e] = c * rsqrtf(v + 1e-5f) * g[e] + bb[e];
    __syncthreads();
    int h = e & 7;
    int es = e >> 3;
    float acc = 0.f;
    #pragma unroll
    for (int ss = 0; ss < 8; ss++){
        int ee = es + ss*16;
        acc += xn[ee] * Wb[ee*H + h];
    }
    red[e] = acc; __syncthreads();
    if (e < 8){
        float t = 0.f;
        #pragma unroll
        for (int ss = 0; ss < 16; ss++) t += red[e + ss*8];
        g_Bp[(e*L + i)*L + j] = t;
    }
}

// ================= fp16 mma.sync GEMM cores ==================================
#define LDSM_OFFS                                                              \
    const uint32_t aoff = (((lane & 7) + ((lane >> 3) & 1)*8)*ASTRIDE          \
                           + (lane >> 4)*16);                                  \
    const uint32_t boff4 = ((lane & 7)*ASTRIDE + ((lane >> 3) & 1)*16          \
                           + (lane >> 4)*8*ASTRIDE);
#define LDSM_OFFS_FK                                                           \
    const uint32_t aoff2 = (((lane & 7) + ((lane >> 3) & 1)*8)*BSTRIDE         \
                            + (lane >> 4)*16);                                 \
    const uint32_t boff4_2 = ((lane & 7)*BSTRIDE + ((lane >> 3) & 1)*16        \
                             + (lane >> 4)*8*BSTRIDE);

#define COMPUTE_ROWB_F16(aBase, bBase)                                         \
    _Pragma("unroll")                                                          \
    for (int kk8 = 0; kk8 < 4; kk8++){                                         \
        uint32_t ksb = kk8*32;                                                 \
        uint32_t a[4][4], b[4][2];                                             \
        _Pragma("unroll")                                                      \
        for (int mt = 0; mt < 4; mt++)                                         \
            ldsm4((aBase) + (wm + mt*16)*ASTRIDE + ksb + aoff,                 \
                  a[mt][0], a[mt][1], a[mt][2], a[mt][3]);                     \
        _Pragma("unroll")                                                      \
        for (int ntp = 0; ntp < 2; ntp++)                                      \
            ldsm4((bBase) + (wn + ntp*16)*ASTRIDE + ksb + boff4,               \
                  b[2*ntp][0], b[2*ntp][1], b[2*ntp+1][0], b[2*ntp+1][1]);     \
        _Pragma("unroll")                                                      \
        for (int mt = 0; mt < 4; mt++)                                         \
            _Pragma("unroll")                                                  \
            for (int nt = 0; nt < 4; nt++)                                     \
                mma_f16(c[mt][nt], a[mt][0],a[mt][1],a[mt][2],a[mt][3],        \
                        b[nt][0], b[nt][1]);                                   \
    }

#define COMPUTE_FK_F16(aBase, bBase)                                           \
    _Pragma("unroll")                                                          \
    for (int kk8 = 0; kk8 < 8; kk8++){                                         \
        uint32_t ksb = kk8*32;                                                 \
        uint32_t a[4][4], b[4][2];                                             \
        _Pragma("unroll")                                                      \
        for (int mt = 0; mt < 4; mt++)                                         \
            ldsm4((aBase) + (wm + mt*16)*BSTRIDE + ksb + aoff2,                \
                  a[mt][0], a[mt][1], a[mt][2], a[mt][3]);                     \
        _Pragma("unroll")                                                      \
        for (int ntp = 0; ntp < 2; ntp++)                                      \
            ldsm4((bBase) + (wn + ntp*16)*BSTRIDE + ksb + boff4_2,             \
                  b[2*ntp][0], b[2*ntp][1], b[2*ntp+1][0], b[2*ntp+1][1]);     \
        _Pragma("unroll")                                                      \
        for (int mt = 0; mt < 4; mt++)                                         \
            _Pragma("unroll")                                                  \
            for (int nt = 0; nt < 4; nt++)                                     \
                mma_f16(c[mt][nt], a[mt][0],a[mt][1],a[mt][2],a[mt][3],        \
                        b[nt][0], b[nt][1]);                                   \
    }

#define COMPUTE_KNB_F16(aBase, bBase)                                          \
    _Pragma("unroll")                                                          \
    for (int kk8 = 0; kk8 < 4; kk8++){                                         \
        uint32_t ksb = kk8*32;                                                 \
        uint32_t a[4][4], b[4][2];                                             \
        _Pragma("unroll")                                                      \
        for (int mt = 0; mt < 4; mt++)                                         \
            ldsm4((aBase) + (wm + mt*16)*ASTRIDE + ksb + aoff,                 \
                  a[mt][0], a[mt][1], a[mt][2], a[mt][3]);                     \
        _Pragma("unroll")                                                      \
        for (int nt = 0; nt < 4; nt++)                                         \
            ldsm2t((bBase) + (kk8*16 + (lane & 15))*BSTRIDE + (wn + nt*8)*2,   \
                   b[nt][0], b[nt][1]);                                        \
        _Pragma("unroll")                                                      \
        for (int mt = 0; mt < 4; mt++)                                         \
            _Pragma("unroll")                                                  \
            for (int nt = 0; nt < 4; nt++)                                     \
                mma_f16(c[mt][nt], a[mt][0],a[mt][1],a[mt][2],a[mt][3],        \
                        b[nt][0], b[nt][1]);                                   \
    }

// -------- kernel 3: projection GEMM, A-resident, 4 n-tiles per CTA -----------
__global__ __launch_bounds__(256) void proj_mma(const float* __restrict__ bg,
                                                int half_sel){
    extern __shared__ char smem[];
    uint32_t sb = (uint32_t)__cvta_generic_to_shared(smem);
    uint32_t sA = sb;
    uint32_t sBb[2] = { sb + FKBYTES, sb + 2*FKBYTES };

    int tid = threadIdx.x;
    int warp = tid >> 5, lane = tid & 31;
    int gid = lane >> 2, tig = lane & 3;
    LDSM_OFFS_FK
    int r0 = blockIdx.x * 128;
    int wm = (warp >> 2) * 64, wn = (warp & 3) * 32;

    #pragma unroll
    for (int it = 0; it < 8; it++){
        int idx = tid + it*256;
        int row = idx >> 4, kq = idx & 15;
        cpa16(sA + row*BSTRIDE + kq*16, &g_Pn[(size_t)(r0+row)*DP + kq*8]);
    }
    CP_COMMIT;

    auto loadB = [&](int t){
        int n0g = half_sel*512 + t*128;
        int which = n0g >> 8;
        const __half* WT = (which==0)?g_WqT:(which==1)?g_WkT:(which==2)?g_WvT:g_WgT;
        int nn0 = n0g & 255;
        uint32_t dst = sBb[t & 1];
        #pragma unroll
        for (int it = 0; it < 8; it++){
            int idx = tid + it*256;
            int row = idx >> 4, kq = idx & 15;
            cpa16(dst + row*BSTRIDE + kq*16, &WT[(size_t)(nn0+row)*DP + kq*8]);
        }
    };
    loadB(0); CP_COMMIT;
    loadB(1); CP_COMMIT;

    const float SQ = 0.17677669529663687f;  // 1/sqrt(DH)
    const float SK = 0.0625f;               // 1/sqrt(L)

    for (int t = 0; t < 4; t++){
        if (t < 3) { CP_WAIT1; } else { CP_WAIT0; }
        __syncthreads();
        float c[4][4][4] = {};
        uint32_t bB = sBb[t & 1];
        COMPUTE_FK_F16(sA, bB);

        int n0g = half_sel*512 + t*128;
        int which = n0g >> 8;
        int nn0 = n0g & 255;
        #pragma unroll
        for (int mt = 0; mt < 4; mt++){
            #pragma unroll
            for (int nt = 0; nt < 4; nt++){
                #pragma unroll
                for (int half = 0; half < 2; half++){
                    int row = r0 + wm + mt*16 + gid + half*8;
                    int a_ = row >> 8, b2 = row & 255;
                    int mm = nn0 + wn + nt*8 + 2*tig;
                    float y0 = c[mt][nt][half*2+0];
                    float y1 = c[mt][nt][half*2+1];
                    if (which == 3){
                        y0 = 1.f/(1.f + expf(-(y0 + bg[mm])));
                        y1 = 1.f/(1.f + expf(-(y1 + bg[mm+1])));
                        __half2 hv = __floats2half2_rn(y0, y1);
                        *(__half2*)&g_G[(size_t)row*HD + mm] = hv;
                    } else {
                        int hh = mm >> 5, cc = mm & 31;
                        size_t dst = (((size_t)hh*L + b2)*L + a_)*DH + cc;
                        float sc = (which==0) ? SQ : (which==1) ? SK : 1.f;
                        __half2 hv = __floats2half2_rn(y0*sc, y1*sc);
                        if      (which==0) *(__half2*)&g_Q[dst] = hv;
                        else if (which==1) *(__half2*)&g_K[dst] = hv;
                        else               *(__half2*)&g_V[dst] = hv;
                    }
                }
            }
        }
        __syncthreads();            // all warps done reading buf (t&1)
        if (t + 2 < 4) loadB(t + 2);
        CP_COMMIT;
    }
}

// -------- kernel 4: QK^T logits, split-K -------------------------------------
__global__ __launch_bounds__(256) void qk_mma(){
    extern __shared__ char smem[];
    uint32_t sb = (uint32_t)__cvta_generic_to_shared(smem);
    uint32_t sA = sb, sB = sb + 3*STG;

    int tid = threadIdx.x;
    int warp = tid >> 5, lane = tid & 31;
    int gid = lane >> 2, tig = lane & 3;
    LDSM_OFFS
    int ks_id = blockIdx.x;
    int tile  = blockIdx.y;
    int i0 = (tile >> 1) * 128, j0 = (tile & 1) * 128;
    int h = blockIdx.z;
    const __half* Qh = g_Q + (size_t)h * (LL*DH);
    const __half* Kh = g_K + (size_t)h * (LL*DH);
    int wm = (warp >> 2) * 64, wn = (warp & 3) * 32;
    float c[4][4][4] = {};
    int kbeg = ks_id * 1024;             // halves

    auto load_stage = [&](int t, int slot){
        int k0 = kbeg + t * 64;
        #pragma unroll
        for (int it = 0; it < 4; it++){
            int idx = tid + it*256;
            int row = idx >> 3, kq = idx & 7;
            cpa16(sA + slot*STG + row*ASTRIDE + kq*16,
                  &Qh[(size_t)(i0+row)*LDH + k0 + kq*8]);
            cpa16(sB + slot*STG + row*ASTRIDE + kq*16,
                  &Kh[(size_t)(j0+row)*LDH + k0 + kq*8]);
        }
    };
    const int NS = 16;
    load_stage(0,0); CP_COMMIT;
    load_stage(1,1); CP_COMMIT;
    for (int s = 0; s < NS; s++){
        CP_WAIT1; __syncthreads();
        if (s + 2 < NS) load_stage(s+2, (s+2)%3);
        CP_COMMIT;
        uint32_t aB = sA + (s%3)*STG, bB = sB + (s%3)*STG;
        COMPUTE_ROWB_F16(aB, bB);
    }

    float* dst = g_Apart + ((size_t)ks_id*H + h) * LL;
    #pragma unroll
    for (int mt = 0; mt < 4; mt++)
        #pragma unroll
        for (int nt = 0; nt < 4; nt++)
            #pragma unroll
            for (int half = 0; half < 2; half++){
                int i = i0 + wm + mt*16 + gid + half*8;
                int j = j0 + wn + nt*8 + 2*tig;
                *(float2*)&dst[(size_t)i*L + j] =
                    make_float2(c[mt][nt][half*2], c[mt][nt][half*2+1]);
            }
}

// -------- kernel 5: reduce split-K + bias + mask + softmax (shfl) ------------
__global__ __launch_bounds__(256) void softmax_fused(const int* __restrict__ mask,
                                                     int i_base){
    int h = blockIdx.x >> 7;
    int i = i_base + (blockIdx.x & 127);
    int row = h*L + i;
    int j = threadIdx.x;       // 256
    int lane = j & 31, warp = j >> 5;
    float v = 0.f;
    #pragma unroll
    for (int s = 0; s < KSPLIT; s++)
        v += g_Apart[(((size_t)s*H + h)*L + i)*L + j];
    v += g_Bp[(size_t)row*L + j];
    if (mask[i] == 0 || mask[j] == 0) v = -1e9f;

    __shared__ float wred[8];
    float mx = v;
    #pragma unroll
    for (int o = 16; o > 0; o >>= 1) mx = fmaxf(mx, __shfl_xor_sync(0xffffffffu, mx, o));
    if (lane == 0) wred[warp] = mx;
    __syncthreads();
    float m0 = wred[lane & 7];
    #pragma unroll
    for (int o = 4; o > 0; o >>= 1) m0 = fmaxf(m0, __shfl_xor_sync(0xffffffffu, m0, o));
    mx = m0;

    float e = expf(v - mx);
    float sm = e;
    #pragma unroll
    for (int o = 16; o > 0; o >>= 1) sm += __shfl_xor_sync(0xffffffffu, sm, o);
    __syncthreads();
    if (lane == 0) wred[warp] = sm;
    __syncthreads();
    float s0 = wred[lane & 7];
    #pragma unroll
    for (int o = 4; o > 0; o >>= 1) s0 += __shfl_xor_sync(0xffffffffu, s0, o);
    g_A[(size_t)row*L + j] = __float2half_rn(e / s0);
}

// -------- kernel 6: AV GEMM + gate (KNB, trans-LDSM on V) --------------------
__global__ __launch_bounds__(256) void av_mma(int i0_base){
    extern __shared__ char smem[];
    uint32_t sb = (uint32_t)__cvta_generic_to_shared(smem);
    uint32_t sA = sb, sB = sb + 3*STG;

    int tid = threadIdx.x;
    int warp = tid >> 5, lane = tid & 31;
    int gid = lane >> 2, tig = lane & 3;
    LDSM_OFFS
    (void)boff4;
    int n0 = blockIdx.x * 128;
    int i0 = i0_base;
    int h  = blockIdx.z;
    const __half* Ah = g_A + (size_t)h * LL;
    const __half* Vh = g_V + (size_t)h * (LL*DH);
    int wm = (warp >> 2) * 64, wn = (warp & 3) * 32;
    float c[4][4][4] = {};

    auto load_stage = [&](int t, int slot){
        int k0 = t * 64;                 // j offset
        #pragma unroll
        for (int it = 0; it < 4; it++){
            int idx = tid + it*256;
            int row = idx >> 3, kq = idx & 7;
            cpa16(sA + slot*STG + row*ASTRIDE + kq*16,
                  &Ah[(size_t)(i0+row)*L + k0 + kq*8]);
            int jl = idx >> 4, nq = idx & 15;
            cpa16(sB + slot*BSTG + jl*BSTRIDE + nq*16,
                  &Vh[(size_t)(k0+jl)*LDH + n0 + nq*8]);
        }
    };
    const int NS = 4;
    load_stage(0,0); CP_COMMIT;
    load_stage(1,1); CP_COMMIT;
    for (int s = 0; s < NS; s++){
        CP_WAIT1; __syncthreads();
        if (s + 2 < NS) load_stage(s+2, (s+2)%3);
        CP_COMMIT;
        uint32_t aB = sA + (s%3)*STG, bB = sB + (s%3)*BSTG;
        COMPUTE_KNB_F16(aB, bB);
    }

    __half* Oh = g_O1 + (size_t)h * (LL*DH);
    #pragma unroll
    for (int mt = 0; mt < 4; mt++)
        #pragma unroll
        for (int nt = 0; nt < 4; nt++)
            #pragma unroll
            for (int half = 0; half < 2; half++){
                int i = i0 + wm + mt*16 + gid + half*8;
                int n = n0 + wn + nt*8 + 2*tig;
                __half2 gg = *(const __half2*)&g_G[((size_t)i*L + (n>>5))*HD + h*DH + (n&31)];
                float2 gf = __half22float2(gg);
                __half2 hv = __floats2half2_rn(c[mt][nt][half*2]   * gf.x,
                                               c[mt][nt][half*2+1] * gf.y);
                *(__half2*)&Oh[(size_t)i*LDH + n] = hv;
            }
}

// -------- kernel 7: (gated out) @ Wo + bo (ROWB via WoT) ----------------------
__global__ __launch_bounds__(256) void final_mma(
        const int* __restrict__ mask, const float* __restrict__ bo,
        float* __restrict__ out, int blk_base){
    extern __shared__ char smem[];
    uint32_t sb = (uint32_t)__cvta_generic_to_shared(smem);
    uint32_t sA = sb, sB = sb + 3*STG;

    int tid = threadIdx.x;
    int warp = tid >> 5, lane = tid & 31;
    int gid = lane >> 2, tig = lane & 3;
    LDSM_OFFS
    int r0 = (blockIdx.x + blk_base) * 128;   // rows r = i*256 + k
    int i  = r0 >> 8;
    int k0r = r0 & 255;
    int wm = (warp >> 2) * 64, wn = (warp & 3) * 32;
    float c[4][4][4] = {};

    auto load_stage = [&](int t, int slot){
        #pragma unroll
        for (int it = 0; it < 4; it++){
            int idx = tid + it*256;
            int row = idx >> 3, kq = idx & 7;
            int hh = 2*t + (kq >> 2), d = (kq & 3)*8;
            cpa16(sA + slot*STG + row*ASTRIDE + kq*16,
                  &g_O1[(size_t)hh*(LL*DH) + (size_t)i*LDH
                        + (size_t)(k0r+row)*DH + d]);
            cpa16(sB + slot*STG + row*ASTRIDE + kq*16,
                  &g_WoT[(size_t)row*HD + t*64 + kq*8]);
        }
    };
    const int NS = 4;
    load_stage(0,0); CP_COMMIT;
    load_stage(1,1); CP_COMMIT;
    for (int s = 0; s < NS; s++){
        CP_WAIT1; __syncthreads();
        if (s + 2 < NS) load_stage(s+2, (s+2)%3);
        CP_COMMIT;
        uint32_t aB = sA + (s%3)*STG, bB = sB + (s%3)*STG;
        COMPUTE_ROWB_F16(aB, bB);
    }

    bool mi = (mask[i] == 0);
    #pragma unroll
    for (int mt = 0; mt < 4; mt++)
        #pragma unroll
        for (int nt = 0; nt < 4; nt++)
            #pragma unroll
            for (int half = 0; half < 2; half++){
                int rowl = wm + mt*16 + gid + half*8;
                int k = k0r + rowl;
                int col = wn + nt*8 + 2*tig;
                float y0 = c[mt][nt][half*2+0] + bo[col];
                float y1 = c[mt][nt][half*2+1] + bo[col+1];
                if (mi || mask[k] == 0){ y0 = 0.f; y1 = 0.f; }
                *(float2*)&out[((size_t)k*L + i)*DP + col] = make_float2(y0, y1);
            }
}

// ---------------------------------------------------------------------------
extern "C" void kernel_launch(void* const* d_in, const int* in_sizes, int n_in,
                              void* d_out, int out_size){
    const float* pair   = (const float*)d_in[0];
    const float* bias   = (const float*)d_in[1];
    const int*   mask   = (const int*)  d_in[2];
    const float* g_pair = (const float*)d_in[3];
    const float* b_pair = (const float*)d_in[4];
    const float* g_bias = (const float*)d_in[5];
    const float* b_bias = (const float*)d_in[6];
    const float* Wq     = (const float*)d_in[7];
    const float* Wk     = (const float*)d_in[8];
    const float* Wv     = (const float*)d_in[9];
    const float* Wb     = (const float*)d_in[10];
    const float* Wg     = (const float*)d_in[11];
    const float* bg     = (const float*)d_in[12];
    const float* Wo     = (const float*)d_in[13];
    const float* bo     = (const float*)d_in[14];
    float* out = (float*)d_out;

    static int inited = 0;
    static cudaStream_t s2, s3;
    static cudaEvent_t ev0, ev1, ev2, ev3, evQK, ev5;
    if (!inited){
        cudaFuncSetAttribute(proj_mma,  cudaFuncAttributeMaxDynamicSharedMemorySize, SMEM_PROJ);
        cudaFuncSetAttribute(qk_mma,    cudaFuncAttributeMaxDynamicSharedMemorySize, SMEM_ROWB);
        cudaFuncSetAttribute(av_mma,    cudaFuncAttributeMaxDynamicSharedMemorySize, SMEM_AV);
        cudaFuncSetAttribute(final_mma, cudaFuncAttributeMaxDynamicSharedMemorySize, SMEM_ROWB);
        cudaStreamCreateWithFlags(&s2, cudaStreamNonBlocking);
        cudaStreamCreateWithFlags(&s3, cudaStreamNonBlocking);
        cudaEventCreateWithFlags(&ev0,  cudaEventDisableTiming);
        cudaEventCreateWithFlags(&ev1,  cudaEventDisableTiming);
        cudaEventCreateWithFlags(&ev2,  cudaEventDisableTiming);
        cudaEventCreateWithFlags(&ev3,  cudaEventDisableTiming);
        cudaEventCreateWithFlags(&evQK, cudaEventDisableTiming);
        cudaEventCreateWithFlags(&ev5,  cudaEventDisableTiming);
        inited = 1;
    }

    // fork side streams (front identical to R14 champion)
    cudaEventRecord(ev0, 0);
    cudaStreamWaitEvent(s2, ev0, 0);
    cudaStreamWaitEvent(s3, ev0, 0);

    bias_proj_kernel<<<LL, 128, 0, s2>>>(bias, g_bias, b_bias, Wb);  // inputs only
    cvt_weights     <<<128, 256, 0, s3>>>(Wq, Wk, Wv, Wg, Wo);       // inputs only
    cudaEventRecord(ev3, s3);

    ln_pair_kernel  <<<LL/8, 256>>>(pair, g_pair, b_pair);
    cudaEventRecord(ev1, 0);

    // projVG on s2 (needs ln + weights); overlaps projQK + qk on main
    cudaStreamWaitEvent(s2, ev1, 0);
    cudaStreamWaitEvent(s2, ev3, 0);
    proj_mma        <<<512, 256, SMEM_PROJ, s2>>>(bg, 1);   // V, G
    cudaEventRecord(ev2, s2);

    cudaStreamWaitEvent(0, ev3, 0);
    proj_mma        <<<512, 256, SMEM_PROJ>>>(bg, 0);       // Q, K
    qk_mma          <<<dim3(KSPLIT, 4, H), 256, SMEM_ROWB>>>();
    cudaEventRecord(evQK, 0);

    // ---- tail pipelined by i halves ----
    cudaStreamWaitEvent(0, ev2, 0);                     // Bp + V + G ready
    softmax_fused   <<<1024, 256>>>(mask, 0);           // i < 128
    av_mma          <<<dim3(64, 1, H), 256, SMEM_AV>>>(0);

    cudaStreamWaitEvent(s2, evQK, 0);                   // s2 has Bp,V,G in-stream
    softmax_fused   <<<1024, 256, 0, s2>>>(mask, 128);  // i >= 128
    av_mma          <<<dim3(64, 1, H), 256, SMEM_AV, s2>>>(128);
    cudaEventRecord(ev5, s2);

    final_mma       <<<256, 256, SMEM_ROWB>>>(mask, bo, out, 0);    // i < 128 (overlaps av_1)
    cudaStreamWaitEvent(0, ev5, 0);
    final_mma       <<<256, 256, SMEM_ROWB>>>(mask, bo, out, 256);  // i >= 128
}